// round 17
// baseline (speedup 1.0000x reference)
#include <cuda_runtime.h>
#include <cstdint>

// ============================================================================
// StochasticLoop: x0 + sum_t uniform(sub_t)  until mean > 100, then *2.
// Exact JAX threefry2x32-20, partitionable semantics (adjudicated: rel_err=0).
//
// R15 perf: R14 ncu still alu=79.9%/fma=22.6% -> ptxas strength-reduced the
// x*2^r rotates back to shifts (compile-time constant). Fix: rotation
// multipliers live in a __device__ array written at RUNTIME by the init
// kernel -> ptxas must emit IMAD.WIDE.U32 (fma pipe). Round cost becomes
// ~1.5 alu + 1.5 fma. Also: grid 1184 -> 740 (5 blocks/SM x 148, single
// uniform wave; 1184 produced a 296-block straggler wave).
// ============================================================================

#define TMAX 204                      // trip count is ~199-200
#define N_ELEMS 20971520u             // 20*1024*1024
#define NQ (N_ELEMS / 4u)             // float4 quads
#define THRESH_SUM 2097152000.0       // 100.0 * N_ELEMS  (mean > 100)

#define GRID_BLOCKS 740               // 148 SMs * 5 resident blocks
#define BLOCK_THREADS 256

__device__ double   g_xsum[TMAX];     // sum of x after iteration t
__device__ uint2    g_subkeys[TMAX];  // per-iteration noise keys
__device__ uint32_t g_rotmul[9];      // runtime 2^r: opaque to ptxas (forces IMAD.WIDE)

// rotation amounts, order: r13,r15,r26,r6, r17,r29,r16,r24, final 2^23
#define RM13 rm[0]
#define RM15 rm[1]
#define RM26 rm[2]
#define RM6  rm[3]
#define RM17 rm[4]
#define RM29 rm[5]
#define RM16 rm[6]
#define RM24 rm[7]
#define RM23 rm[8]

// ---------------- threefry2x32-20 helpers (hot path) ----------------

// rotl(x,r) ^ y via one IMAD.WIDE.U32 (m = 2^r runtime reg) + one LOP3
__device__ __forceinline__ uint32_t rotxor(uint32_t x, uint32_t m, uint32_t y) {
    const uint64_t p = (uint64_t)x * (uint64_t)m;   // IMAD.WIDE.U32 (fma pipe)
    return ((uint32_t)p | (uint32_t)(p >> 32)) ^ y; // single LOP3 (alu pipe)
}

#define TF_RND(m) { x0 += x1; x1 = rotxor(x1, (m), x0); }

__device__ __forceinline__ void tf_block_m(uint32_t k0, uint32_t k1, uint32_t k2,
                                           uint32_t c1, const uint32_t* __restrict__ rm,
                                           uint32_t& o0, uint32_t& o1) {
    uint32_t x0 = k0, x1 = c1 + k1;          // c0 == 0 always in this problem
    TF_RND(RM13) TF_RND(RM15) TF_RND(RM26) TF_RND(RM6)
    x0 += k1; x1 += k2 + 1u;
    TF_RND(RM17) TF_RND(RM29) TF_RND(RM16) TF_RND(RM24)
    x0 += k2; x1 += k0 + 2u;
    TF_RND(RM13) TF_RND(RM15) TF_RND(RM26) TF_RND(RM6)
    x0 += k0; x1 += k1 + 3u;
    TF_RND(RM17) TF_RND(RM29) TF_RND(RM16) TF_RND(RM24)
    x0 += k1; x1 += k2 + 4u;
    TF_RND(RM13) TF_RND(RM15) TF_RND(RM26) TF_RND(RM6)
    x0 += k2; x1 += k0 + 5u;
    o0 = x0; o1 = x1;
}

// x' = x + u,  u = ((o0^o1)>>9) * 2^-23 exactly; >>9 as hi word of *2^23
// (IMAD.WIDE, fma pipe), then one I2F + one FFMA (single-rounded == FADD).
__device__ __forceinline__ float add_u01(float x, uint32_t o0, uint32_t o1,
                                         uint32_t m23) {
    const uint64_t p = (uint64_t)(o0 ^ o1) * (uint64_t)m23;
    return fmaf((float)(uint32_t)(p >> 32), 0x1p-23f, x);
}

// ---------------- init: zero sums, key chain, rotate multipliers ------------

__device__ __forceinline__ void tf_block_ref(uint32_t k0, uint32_t k1,
                                             uint32_t c0, uint32_t c1,
                                             uint32_t& o0, uint32_t& o1) {
    const uint32_t k2 = k0 ^ k1 ^ 0x1BD11BDAu;
    uint32_t x0 = c0 + k0, x1 = c1 + k1;
#define TF_R(r) { x0 += x1; x1 = __funnelshift_l(x1, x1, r); x1 ^= x0; }
    TF_R(13) TF_R(15) TF_R(26) TF_R(6)   x0 += k1; x1 += k2 + 1u;
    TF_R(17) TF_R(29) TF_R(16) TF_R(24)  x0 += k2; x1 += k0 + 2u;
    TF_R(13) TF_R(15) TF_R(26) TF_R(6)   x0 += k0; x1 += k1 + 3u;
    TF_R(17) TF_R(29) TF_R(16) TF_R(24)  x0 += k1; x1 += k2 + 4u;
    TF_R(13) TF_R(15) TF_R(26) TF_R(6)   x0 += k2; x1 += k0 + 5u;
#undef TF_R
    o0 = x0; o1 = x1;
}

__global__ void sl_init_kernel() {
    for (int i = threadIdx.x; i < TMAX; i += blockDim.x) g_xsum[i] = 0.0;
    if (threadIdx.x == 0) {
        // runtime-written rotate multipliers (opaque to ptxas in iter kernel)
        const int rots[8] = {13, 15, 26, 6, 17, 29, 16, 24};
        for (int i = 0; i < 8; ++i) g_rotmul[i] = 1u << rots[i];
        g_rotmul[8] = 1u << 23;

        uint32_t k0 = 0u, k1 = 42u;   // jax.random.key(42) -> (hi=0, lo=42)
        for (int t = 0; t < TMAX; ++t) {
            // split(k,2): keys[0]=block(k,0,0) -> next key; keys[1]=block(k,0,1) -> subkey
            uint32_t n0, n1, s0, s1;
            tf_block_ref(k0, k1, 0u, 0u, n0, n1);
            tf_block_ref(k0, k1, 0u, 1u, s0, s1);
            g_subkeys[t] = make_uint2(s0, s1);
            k0 = n0; k1 = n1;
        }
    }
}

// ---------------- one loop iteration (noise add + global sum) ----------------

__global__ void __launch_bounds__(BLOCK_THREADS, 5)
sl_iter_kernel(float* __restrict__ out, const float* __restrict__ xin, int t) {
    if (t > 0) {
        const double prev = g_xsum[t - 1];
        if (prev > THRESH_SUM) {            // mean already > 100: loop halted
            if (threadIdx.x == 0) g_xsum[t] = prev;  // forward (same value from all blocks)
            return;
        }
    }
    const float* __restrict__ src = (t == 0) ? xin : out;
    const uint2 sk = g_subkeys[t];
    const uint32_t k0 = sk.x, k1 = sk.y;
    const uint32_t k2 = k0 ^ k1 ^ 0x1BD11BDAu;

    // load opaque rotate multipliers once (uniform across threads -> URs)
    uint32_t rm[9];
#pragma unroll
    for (int i = 0; i < 9; ++i) rm[i] = g_rotmul[i];
    const uint32_t m23 = RM23;

    float s = 0.0f;                        // fp32 accumulation (margin ~1e6 >> err <1)
    const uint32_t stride = gridDim.x * blockDim.x;

    for (uint32_t q = blockIdx.x * blockDim.x + threadIdx.x; q < NQ; q += stride) {
        const uint32_t i = q * 4u;
        float4 v = *reinterpret_cast<const float4*>(src + i);
        uint32_t a0, a1, b0, b1, c0, c1, d0, d1;
        tf_block_m(k0, k1, k2, i + 0u, rm, a0, a1);
        tf_block_m(k0, k1, k2, i + 1u, rm, b0, b1);
        tf_block_m(k0, k1, k2, i + 2u, rm, c0, c1);
        tf_block_m(k0, k1, k2, i + 3u, rm, d0, d1);
        v.x = add_u01(v.x, a0, a1, m23);
        v.y = add_u01(v.y, b0, b1, m23);
        v.z = add_u01(v.z, c0, c1, m23);
        v.w = add_u01(v.w, d0, d1, m23);
        *reinterpret_cast<float4*>(out + i) = v;
        s += (v.x + v.y) + (v.z + v.w);
    }

    // block reduction (fp32) -> one double atomicAdd per block
#pragma unroll
    for (int o = 16; o > 0; o >>= 1)
        s += __shfl_xor_sync(0xffffffffu, s, o);
    __shared__ float wsum[BLOCK_THREADS / 32];
    const int warp = threadIdx.x >> 5;
    if ((threadIdx.x & 31) == 0) wsum[warp] = s;
    __syncthreads();
    if (threadIdx.x == 0) {
        float tot = 0.0f;
#pragma unroll
        for (int w = 0; w < BLOCK_THREADS / 32; ++w) tot += wsum[w];
        atomicAdd(&g_xsum[t], (double)tot);
    }
}

// ---------------- finalize: x * 2 ----------------

__global__ void __launch_bounds__(BLOCK_THREADS, 5)
sl_finalize_kernel(float* __restrict__ out) {
    const uint32_t stride = gridDim.x * blockDim.x;
    for (uint32_t q = blockIdx.x * blockDim.x + threadIdx.x; q < NQ; q += stride) {
        float4 v = *reinterpret_cast<float4*>(out + q * 4u);
        v.x *= 2.0f; v.y *= 2.0f; v.z *= 2.0f; v.w *= 2.0f;
        *reinterpret_cast<float4*>(out + q * 4u) = v;
    }
}

// ---------------- launch ----------------

extern "C" void kernel_launch(void* const* d_in, const int* in_sizes, int n_in,
                              void* d_out, int out_size) {
    const float* x = (const float*)d_in[0];
    float* out = (float*)d_out;

    sl_init_kernel<<<1, 256>>>();
    for (int t = 0; t < TMAX; ++t)
        sl_iter_kernel<<<GRID_BLOCKS, BLOCK_THREADS>>>(out, x, t);
    sl_finalize_kernel<<<GRID_BLOCKS, BLOCK_THREADS>>>(out);
}